// round 10
// baseline (speedup 1.0000x reference)
#include <cuda_runtime.h>
#include <cuda_bf16.h>
#include <stdint.h>

#define BS   16
#define MM   128
#define NA   8400
#define NC   80
#define KTOP 13
#define CAP  1024
#define NROW (BS * MM)
#define EPS7 1e-7f
#define EPS9 1e-9f
#define FULL 0xffffffffu
#define CNT1 (1 << 20)

// scratch (static device globals -- allowed)
__device__ int    g_cs  [BS * NA];
__device__ float  g_alsum[BS * NA];
__device__ float  g_ovsum[BS * NA];
__device__ unsigned long long g_best[BS * NA];
__device__ unsigned long long g_cand[(size_t)NROW * CAP];
__device__ int    g_ccount[NROW];
__device__ float  g_pos_am[NROW];
__device__ float  g_pos_ov[NROW];
__device__ int    g_tgt[BS * NA];
__device__ float  g_al [BS * NA];
__device__ int    g_fglist[BS * NA];
__device__ int    g_multilist[BS * NA];
__device__ int    g_nfg;
__device__ int    g_nmulti;
__device__ float4 g_gtbox[NROW];
__device__ float4 g_gtaux[NROW];      // {at1, mask, label(int bits), 0}
__device__ int4   g_rA[NROW];         // {ix0_0, iy0_0, w0, t0}
__device__ int4   g_rB[NROW];         // {ix0_1, iy0_1, w1, t0+t1}
__device__ int4   g_rC[NROW];         // {ix0_2, iy0_2, w2, tot}
__device__ int    g_rowoff[NROW + 1]; // exclusive prefix of tot

// ---------------------------------------------------------------------------
__device__ __forceinline__ float ciou_core(const float4 g, const float4 p,
                                           float at_g, float at_p)
{
    const float c4pi2 = 0.40528473456935108577f;
    float w1 = g.z - g.x, h1 = g.w - g.y + EPS7;
    float w2 = p.z - p.x, h2 = p.w - p.y + EPS7;
    float iw = fminf(g.z, p.z) - fmaxf(g.x, p.x);
    float ih = fminf(g.w, p.w) - fmaxf(g.y, p.y);
    float inter = fmaxf(iw, 0.f) * fmaxf(ih, 0.f);
    float uni = w1 * h1 + w2 * h2 - inter + EPS7;
    float iou = inter / uni;
    float cw = fmaxf(g.z, p.z) - fminf(g.x, p.x);
    float ch = fmaxf(g.w, p.w) - fminf(g.y, p.y);
    float c2 = cw * cw + ch * ch + EPS7;
    float dx = p.x + p.z - g.x - g.z;
    float dy = p.y + p.w - g.y - g.w;
    float rho2 = (dx * dx + dy * dy) * 0.25f;
    float dat = at_p - at_g;
    float v = c4pi2 * dat * dat;
    float alpha = v / (v - iou + (1.f + EPS7));
    return fmaxf(iou - (rho2 / c2 + v * alpha), 0.f);
}
__device__ __forceinline__ float ciou_hg(const float4 g, const float4 p, float at_g)
{
    return ciou_core(g, p, at_g, atanf((p.z - p.x) / (p.w - p.y + EPS7)));
}
__device__ __forceinline__ float dmin_xy(const float4 g, float ax, float ay)
{
    return fminf(fminf(ax - g.x, ay - g.y), fminf(g.z - ax, g.w - ay));
}

// ---------------------------------------------------------------------------
// KZ (side stream): zero per-anchor accumulators
// ---------------------------------------------------------------------------
__global__ __launch_bounds__(256) void kz_zero()
{
    int i = blockIdx.x * blockDim.x + threadIdx.x;
    if (i < BS * NA) { g_cs[i] = 0; g_alsum[i] = 0.f; g_ovsum[i] = 0.f; }
}

// ---------------------------------------------------------------------------
// K0p: ONE block, 1024 threads: GT table, rect tables, prefix scan of tot
// ---------------------------------------------------------------------------
__global__ __launch_bounds__(1024) void k0p(
    const int*   __restrict__ gt_labels,
    const float* __restrict__ gt_bboxes,
    const float* __restrict__ mask_gt)
{
    __shared__ int sa[NROW], sb[NROW];
    int tid = threadIdx.x;

    #pragma unroll
    for (int rr = 0; rr < 2; ++rr) {
        int i = tid + rr * 1024;
        g_ccount[i] = 0;
        g_pos_am[i] = 0.f; g_pos_ov[i] = 0.f;
        float4 g = reinterpret_cast<const float4*>(gt_bboxes)[i];
        float msk = mask_gt[i];
        g_gtbox[i] = g;
        float4 aux;
        aux.x = atanf((g.z - g.x) / (g.w - g.y + EPS7));
        aux.y = msk;
        aux.z = __int_as_float(gt_labels[i]);
        aux.w = 0.f;
        g_gtaux[i] = aux;

        int tot = 0;
        int4 rA = {0,0,0,0}, rB = {0,0,0,0}, rC = {0,0,0,0};
        if (msk > 0.f) {
            int t0 = 0, t01 = 0;
            #pragma unroll
            for (int ks = 0; ks < 3; ++ks) {
                const int   n = (ks == 0) ? 80 : (ks == 1) ? 40 : 20;
                const float s = (ks == 0) ? 8.f : (ks == 1) ? 16.f : 32.f;
                int ix0 = max(0,     (int)floorf(g.x / s - 0.5f));
                int ix1 = min(n - 1, (int)floorf(g.z / s - 0.5f) + 1);
                int iy0 = max(0,     (int)floorf(g.y / s - 0.5f));
                int iy1 = min(n - 1, (int)floorf(g.w / s - 0.5f) + 1);
                int w = max(ix1 - ix0 + 1, 0), h = max(iy1 - iy0 + 1, 0);
                int c = w * h;
                if (ks == 0) { rA = make_int4(ix0, iy0, w, c); t0 = c; }
                if (ks == 1) { t01 = t0 + c; rB = make_int4(ix0, iy0, w, t01); }
                if (ks == 2) { rC = make_int4(ix0, iy0, w, t01 + c); }
                tot += c;
            }
        } else {
            rA.w = 0; rB.w = 0; rC.w = 0;
        }
        g_rA[i] = rA; g_rB[i] = rB; g_rC[i] = rC;
        sa[i] = tot;
    }
    __syncthreads();

    // inclusive Hillis-Steele scan over 2048 entries
    int* src = sa; int* dst = sb;
    for (int d = 1; d < NROW; d <<= 1) {
        #pragma unroll
        for (int rr = 0; rr < 2; ++rr) {
            int i = tid + rr * 1024;
            int v = src[i];
            if (i >= d) v += src[i - d];
            dst[i] = v;
        }
        __syncthreads();
        int* tmp = src; src = dst; dst = tmp;
    }
    #pragma unroll
    for (int rr = 0; rr < 2; ++rr) {
        int i = tid + rr * 1024;
        g_rowoff[i + 1] = src[i];
    }
    if (tid == 0) { g_rowoff[0] = 0; g_nfg = 0; g_nmulti = 0; }
}

// ---------------------------------------------------------------------------
// K1a: one THREAD per live rect cell (flattened via g_rowoff). Positives
// pushed into per-row candidate buffers as packed keys.
// ---------------------------------------------------------------------------
__global__ __launch_bounds__(256) void k1a(
    const float* __restrict__ pd_scores,
    const float* __restrict__ pd_bboxes)
{
    int total = g_rowoff[NROW];
    int stride = gridDim.x * blockDim.x;
    for (int t = blockIdx.x * 256 + threadIdx.x; t < total; t += stride) {
        int lo = 0, hi = NROW;
        #pragma unroll
        for (int it = 0; it < 11; ++it) {
            int mid = (lo + hi) >> 1;
            if (g_rowoff[mid] <= t) lo = mid; else hi = mid;
        }
        int row = lo, tc = t - g_rowoff[row];

        int4 rA = g_rA[row], rB = g_rB[row], rC = g_rC[row];
        int n, off, ix, iy; float s;
        if (tc < rA.w) {
            n = 80; s = 8.f; off = 0;
            ix = rA.x + tc % rA.z; iy = rA.y + tc / rA.z;
        } else if (tc < rB.w) {
            int u = tc - rA.w;
            n = 40; s = 16.f; off = 6400;
            ix = rB.x + u % rB.z; iy = rB.y + u / rB.z;
        } else {
            int u = tc - rB.w;
            n = 20; s = 32.f; off = 8000;
            ix = rC.x + u % rC.z; iy = rC.y + u / rC.z;
        }
        float ax = (ix + 0.5f) * s, ay = (iy + 0.5f) * s;
        float4 g = g_gtbox[row];
        if (dmin_xy(g, ax, ay) <= EPS9) continue;

        float4 aux = g_gtaux[row];
        int b = row >> 7;
        int idx = off + iy * n + ix;
        float4 p = reinterpret_cast<const float4*>(pd_bboxes)[(size_t)b * NA + idx];
        float ov = ciou_core(g, p, aux.x,
                             atanf((p.z - p.x) / (p.w - p.y + EPS7)));
        if (ov <= 0.f) continue;
        int lbl = __float_as_int(aux.z);
        float sc = pd_scores[((size_t)b * NA + idx) * NC + lbl];
        float o2 = ov * ov;
        float al = sc * (o2 * o2 * o2);
        if (al <= 0.f) continue;

        int slot = atomicAdd(&g_ccount[row], 1);
        if (slot < CAP)
            g_cand[(size_t)row * CAP + slot] =
                ((unsigned long long)__float_as_uint(al) << 32) |
                (unsigned)(0x7fffffff - idx);
    }
}

// ---------------------------------------------------------------------------
// K1b: one WARP per row: batched candidate loads (MLP=8) + per-lane sorted
// top-13, then 13 butterfly selection rounds; claims carry al + ov.
// ---------------------------------------------------------------------------
__global__ __launch_bounds__(256) void k1b(
    const float* __restrict__ pd_bboxes,
    const float* __restrict__ mask_gt)
{
    int wid = threadIdx.x >> 5, lane = threadIdx.x & 31;
    int row = blockIdx.x * 8 + wid;
    if (row >= NROW) return;
    if (mask_gt[row] <= 0.f) return;
    int b = row >> 7, m = row & 127;

    int ncand = min(g_ccount[row], CAP);
    const unsigned long long* cp = g_cand + (size_t)row * CAP;

    unsigned long long keys[KTOP];
    #pragma unroll
    for (int j = 0; j < KTOP; ++j) keys[j] = 0ull;

    for (int base = 0; base < ncand; base += 256) {
        unsigned long long buf[8];
        #pragma unroll
        for (int q = 0; q < 8; ++q) {
            int p = base + lane + q * 32;
            buf[q] = (p < ncand) ? cp[p] : 0ull;
        }
        #pragma unroll
        for (int q = 0; q < 8; ++q) {
            unsigned long long ck = buf[q];
            if (ck > keys[KTOP - 1]) {
                #pragma unroll
                for (int j = 0; j < KTOP; ++j) {
                    unsigned long long kj = keys[j];
                    if (ck > kj) { keys[j] = ck; ck = kj; }
                }
            }
        }
    }

    int   mysel = -1;
    float myval = 0.f;
    int qsel = 0;
    #pragma unroll 1
    for (int it = 0; it < KTOP; ++it) {
        unsigned long long k = keys[0];
        #pragma unroll
        for (int d = 16; d; d >>= 1) {
            unsigned long long o = __shfl_xor_sync(FULL, k, d);
            if (o > k) k = o;
        }
        if ((unsigned)(k >> 32) == 0u) break;
        if (lane == qsel) {
            mysel = 0x7fffffff - (int)(k & 0xffffffffu);
            myval = __uint_as_float((unsigned)(k >> 32));
        }
        qsel++;
        if (keys[0] == k) {
            #pragma unroll
            for (int j = 0; j < KTOP - 1; ++j) keys[j] = keys[j + 1];
            keys[KTOP - 1] = 0ull;
        }
    }

    float4 g = g_gtbox[row];
    float at1 = g_gtaux[row].x;

    if (lane < qsel) {
        float4 p = reinterpret_cast<const float4*>(pd_bboxes)[(size_t)b * NA + mysel];
        float ov = ciou_hg(g, p, at1);
        atomicAdd(&g_cs   [b * NA + mysel], CNT1 | m);
        atomicAdd(&g_alsum[b * NA + mysel], myval);
        atomicAdd(&g_ovsum[b * NA + mysel], ov);
    }

    // zero-fill (rare): smallest-index zero-valued anchors of the full row
    if (qsel < KTOP) {
        int sarr[KTOP];
        for (int t = 0; t < qsel; ++t)
            sarr[t] = __shfl_sync(FULL, mysel, t);
        if (lane == 0) {
            const float4* pbb = reinterpret_cast<const float4*>(pd_bboxes) + (size_t)b * NA;
            int need = KTOP - qsel;
            int j = 0;
            while (need > 0 && j < 8 * KTOP) {
                bool ispos = false;
                for (int t = 0; t < qsel; ++t) if (sarr[t] == j) { ispos = true; break; }
                if (!ispos) {
                    int ix = j % 80, iy = j / 80;
                    float ax = (ix + 0.5f) * 8.f, ay = (iy + 0.5f) * 8.f;
                    if (dmin_xy(g, ax, ay) > EPS9) {
                        float ov = ciou_hg(g, pbb[j], at1);
                        atomicAdd(&g_cs   [b * NA + j], CNT1 | m);
                        atomicAdd(&g_ovsum[b * NA + j], ov);
                    }
                    need--;
                }
                j++;
            }
        }
    }
}

// ---------------------------------------------------------------------------
// K3a: per (b,a). cnt<=1 resolved with carried sums; lists appended with
// warp-aggregated atomics; multi entries seed g_best.
// ---------------------------------------------------------------------------
__global__ __launch_bounds__(256) void k3a(float* __restrict__ out)
{
    int idx = blockIdx.x * blockDim.x + threadIdx.x;   // grid == BS*NA
    int lane = threadIdx.x & 31;
    int b = idx / NA;

    int cs = g_cs[idx];
    int cnt = cs >> 20;
    bool is_multi = cnt > 1;
    bool is_fg1   = cnt == 1;

    unsigned mmask = __ballot_sync(FULL, is_multi);
    if (mmask) {
        int leader = __ffs(mmask) - 1;
        int base = 0;
        if (lane == leader) base = atomicAdd(&g_nmulti, __popc(mmask));
        base = __shfl_sync(FULL, base, leader);
        if (is_multi) {
            int p = base + __popc(mmask & ((1u << lane) - 1));
            g_multilist[p] = idx;
            g_best[p] = (unsigned long long)(MM - 1);  // v=0, m=0 default
        }
    }
    unsigned fmask = __ballot_sync(FULL, is_fg1);
    if (fmask) {
        int leader = __ffs(fmask) - 1;
        int base = 0;
        if (lane == leader) base = atomicAdd(&g_nfg, __popc(fmask));
        base = __shfl_sync(FULL, base, leader);
        if (is_fg1)
            g_fglist[base + __popc(fmask & ((1u << lane) - 1))] = idx;
    }
    if (is_multi) return;

    int fg = cnt, tgt = 0;
    float al = 0.f;
    if (is_fg1) {
        tgt = cs & 0xfffff;
        al  = g_alsum[idx];
        float ovm = g_ovsum[idx];
        int row = b * MM + tgt;
        atomicMax((unsigned int*)&g_pos_am[row], __float_as_uint(al));
        atomicMax((unsigned int*)&g_pos_ov[row], __float_as_uint(ovm));
    }
    g_tgt[idx] = tgt;
    g_al [idx] = al;

    int grow = b * MM + tgt;
    int lbl = max(__float_as_int(g_gtaux[grow].z), 0);
    float4 bx = g_gtbox[grow];
    float* o_lab = out;
    float* o_box = out + (size_t)BS * NA;
    float* o_fg  = out + (size_t)BS * NA * (5 + NC);
    float* o_tg  = o_fg + (size_t)BS * NA;
    o_lab[idx] = (float)lbl;
    reinterpret_cast<float4*>(o_box)[idx] = bx;
    o_fg[idx] = fg ? 1.f : 0.f;
    o_tg[idx] = (float)tgt;
}

// ---------------------------------------------------------------------------
// K3b1: one THREAD per (entry, m): masked CIoU; atomicMax packed key only
// when v>0.
// ---------------------------------------------------------------------------
__global__ __launch_bounds__(256) void k3b1(
    const float* __restrict__ pd_bboxes,
    const float* __restrict__ anc)
{
    int tot = g_nmulti * MM;
    int stride = gridDim.x * blockDim.x;
    for (int t = blockIdx.x * blockDim.x + threadIdx.x; t < tot; t += stride) {
        int e = t >> 7, m = t & 127;
        int idx = g_multilist[e];
        int b = idx / NA, a = idx - b * NA;
        int row = b * MM + m;
        float4 aux = g_gtaux[row];
        if (aux.y <= 0.f) continue;
        float2 an = reinterpret_cast<const float2*>(anc)[a];
        float4 gg = g_gtbox[row];
        if (dmin_xy(gg, an.x, an.y) <= EPS9) continue;
        float4 p = reinterpret_cast<const float4*>(pd_bboxes)[idx];
        float at2 = atanf((p.z - p.x) / (p.w - p.y + EPS7));
        float v = ciou_core(gg, p, aux.x, at2);
        if (v > 0.f) {
            unsigned long long key =
                ((unsigned long long)__float_as_uint(v) << 32) |
                (unsigned)(MM - 1 - m);
            atomicMax(&g_best[e], key);
        }
    }
}

// ---------------------------------------------------------------------------
// K3b2: one thread per entry: unpack winner, finish entry.
// ---------------------------------------------------------------------------
__global__ __launch_bounds__(256) void k3b2(
    const float* __restrict__ pd_scores,
    float* __restrict__ out)
{
    int nm = g_nmulti;
    int stride = gridDim.x * blockDim.x;
    for (int e = blockIdx.x * blockDim.x + threadIdx.x; e < nm; e += stride) {
        int idx = g_multilist[e];
        int b = idx / NA, a = idx - b * NA;
        unsigned long long k = g_best[e];
        int tgt = MM - 1 - (int)(k & 0xffffffffu);
        float ovm = __uint_as_float((unsigned)(k >> 32));
        int row = b * MM + tgt;
        int lbl = __float_as_int(g_gtaux[row].z);
        float al = 0.f;
        if (ovm > 0.f) {
            float sc = pd_scores[((size_t)b * NA + a) * NC + lbl];
            float o2 = ovm * ovm;
            al = sc * (o2 * o2 * o2);
        }
        atomicMax((unsigned int*)&g_pos_am[row], __float_as_uint(al));
        atomicMax((unsigned int*)&g_pos_ov[row], __float_as_uint(ovm));
        g_tgt[idx] = tgt;
        g_al [idx] = al;
        int qq = atomicAdd(&g_nfg, 1);
        g_fglist[qq] = idx;

        float4 bx = g_gtbox[row];
        float* o_lab = out;
        float* o_box = out + (size_t)BS * NA;
        float* o_fg  = out + (size_t)BS * NA * (5 + NC);
        float* o_tg  = o_fg + (size_t)BS * NA;
        o_lab[idx] = (float)max(lbl, 0);
        reinterpret_cast<float4*>(o_box)[idx] = bx;
        o_fg[idx] = 1.f;
        o_tg[idx] = (float)tgt;
    }
}

// ---------------------------------------------------------------------------
// K4: sparse nrm scatter over the compacted fg list (scores pre-zeroed)
// ---------------------------------------------------------------------------
__global__ __launch_bounds__(256) void k4_scatter(float* __restrict__ out)
{
    float* o_sc = out + (size_t)BS * NA * 5;
    int nfg = g_nfg;
    int stride = gridDim.x * blockDim.x;
    for (int i = blockIdx.x * blockDim.x + threadIdx.x; i < nfg; i += stride) {
        int idx = g_fglist[i];
        int b = idx / NA;
        int tgt = g_tgt[idx];
        int grow = b * MM + tgt;
        int lbl = max(__float_as_int(g_gtaux[grow].z), 0);
        float nrm = g_al[idx] * g_pos_ov[grow] / (g_pos_am[grow] + EPS9);
        o_sc[(size_t)idx * NC + lbl] = nrm;
    }
}

// ---------------------------------------------------------------------------
extern "C" void kernel_launch(void* const* d_in, const int* in_sizes, int n_in,
                              void* d_out, int out_size)
{
    const float* pd_scores = (const float*)d_in[0];
    const float* pd_bboxes = (const float*)d_in[1];
    const float* anc       = (const float*)d_in[2];
    const int*   gt_labels = (const int*)  d_in[3];
    const float* gt_bboxes = (const float*)d_in[4];
    const float* mask_gt   = (const float*)d_in[5];
    float* out = (float*)d_out;

    static cudaStream_t s2 = nullptr;
    static cudaEvent_t evFork = nullptr, evZ = nullptr, evJoin = nullptr;
    if (!s2) {
        cudaStreamCreateWithFlags(&s2, cudaStreamNonBlocking);
        cudaEventCreateWithFlags(&evFork, cudaEventDisableTiming);
        cudaEventCreateWithFlags(&evZ,    cudaEventDisableTiming);
        cudaEventCreateWithFlags(&evJoin, cudaEventDisableTiming);
    }

    float* o_sc = out + (size_t)BS * NA * 5;
    int n = BS * NA;

    cudaEventRecord(evFork, 0);
    cudaStreamWaitEvent(s2, evFork, 0);
    kz_zero<<<(n + 255) / 256, 256, 0, s2>>>();
    cudaEventRecord(evZ, s2);
    cudaMemsetAsync(o_sc, 0, (size_t)BS * NA * NC * sizeof(float), s2);
    cudaEventRecord(evJoin, s2);

    k0p<<<1, 1024>>>(gt_labels, gt_bboxes, mask_gt);
    k1a<<<2048, 256>>>(pd_scores, pd_bboxes);
    cudaStreamWaitEvent(0, evZ, 0);
    k1b<<<(NROW + 7) / 8, 256>>>(pd_bboxes, mask_gt);
    k3a<<<n / 256, 256>>>(out);
    k3b1<<<2048, 256>>>(pd_bboxes, anc);
    k3b2<<<64, 256>>>(pd_scores, out);
    cudaStreamWaitEvent(0, evJoin, 0);
    k4_scatter<<<64, 256>>>(out);
}

// round 11
// speedup vs baseline: 1.2248x; 1.2248x over previous
#include <cuda_runtime.h>
#include <cuda_bf16.h>
#include <stdint.h>

#define BS   16
#define MM   128
#define NA   8400
#define NC   80
#define KTOP 13
#define CAP  1024
#define EPS7 1e-7f
#define EPS9 1e-9f
#define FULL 0xffffffffu
#define CNT1 (1 << 20)   // packed claim increment: cnt in high bits, sum(m) low

// scratch (static device globals -- allowed)
__device__ int    g_cs  [BS * NA];    // packed: (cnt<<20) | sum_of_m
__device__ float  g_alsum[BS * NA];
__device__ float  g_ovsum[BS * NA];
__device__ unsigned long long g_best[BS * NA];
__device__ unsigned long long g_cand[(size_t)BS * MM * CAP];
__device__ int    g_ccount[BS * MM];
__device__ float  g_pos_am[BS * MM];
__device__ float  g_pos_ov[BS * MM];
__device__ int    g_tgt[BS * NA];
__device__ float  g_al [BS * NA];
__device__ int    g_fglist[BS * NA];
__device__ int    g_multilist[BS * NA];
__device__ int    g_nfg;
__device__ int    g_nmulti;
__device__ float4 g_gtbox[BS * MM];   // gt box
__device__ float4 g_gtaux[BS * MM];   // {at1, mask, label(int bits), unused}

// ---------------------------------------------------------------------------
// CIoU (identical math to reference _ciou + clip>=0)
// ---------------------------------------------------------------------------
__device__ __forceinline__ float ciou_core(const float4 g, const float4 p,
                                           float at_g, float at_p)
{
    const float c4pi2 = 0.40528473456935108577f;  // 4/pi^2
    float w1 = g.z - g.x, h1 = g.w - g.y + EPS7;
    float w2 = p.z - p.x, h2 = p.w - p.y + EPS7;
    float iw = fminf(g.z, p.z) - fmaxf(g.x, p.x);
    float ih = fminf(g.w, p.w) - fmaxf(g.y, p.y);
    float inter = fmaxf(iw, 0.f) * fmaxf(ih, 0.f);
    float uni = w1 * h1 + w2 * h2 - inter + EPS7;
    float iou = inter / uni;
    float cw = fmaxf(g.z, p.z) - fminf(g.x, p.x);
    float ch = fmaxf(g.w, p.w) - fminf(g.y, p.y);
    float c2 = cw * cw + ch * ch + EPS7;
    float dx = p.x + p.z - g.x - g.z;
    float dy = p.y + p.w - g.y - g.w;
    float rho2 = (dx * dx + dy * dy) * 0.25f;
    float dat = at_p - at_g;
    float v = c4pi2 * dat * dat;
    float alpha = v / (v - iou + (1.f + EPS7));
    return fmaxf(iou - (rho2 / c2 + v * alpha), 0.f);
}
__device__ __forceinline__ float ciou_hg(const float4 g, const float4 p, float at_g)
{
    return ciou_core(g, p, at_g, atanf((p.z - p.x) / (p.w - p.y + EPS7)));
}
__device__ __forceinline__ float dmin_xy(const float4 g, float ax, float ay)
{
    return fminf(fminf(ax - g.x, ay - g.y), fminf(g.z - ax, g.w - ay));
}

// ---------------------------------------------------------------------------
// K0: zero scratch + build GT prep table
// ---------------------------------------------------------------------------
__global__ __launch_bounds__(256) void k0_zero(
    const int*   __restrict__ gt_labels,
    const float* __restrict__ gt_bboxes,
    const float* __restrict__ mask_gt)
{
    int i = blockIdx.x * blockDim.x + threadIdx.x;
    if (i < BS * NA) {
        g_cs[i] = 0;
        g_alsum[i] = 0.f; g_ovsum[i] = 0.f;
    }
    if (i < BS * MM) {
        g_ccount[i] = 0;
        g_pos_am[i] = 0.f; g_pos_ov[i] = 0.f;
        float4 g = reinterpret_cast<const float4*>(gt_bboxes)[i];
        g_gtbox[i] = g;
        float4 aux;
        aux.x = atanf((g.z - g.x) / (g.w - g.y + EPS7));
        aux.y = mask_gt[i];
        aux.z = __int_as_float(gt_labels[i]);
        aux.w = 0.f;
        g_gtaux[i] = aux;
    }
    if (i == 0) { g_nfg = 0; g_nmulti = 0; }
}

// ---------------------------------------------------------------------------
// K1a: one THREAD per (row, rect-cell). Positive align metrics pushed into
// per-row candidate buffers as packed keys.
// ---------------------------------------------------------------------------
__global__ __launch_bounds__(256) void k1a(
    const float* __restrict__ pd_scores,
    const float* __restrict__ pd_bboxes,
    const int*   __restrict__ gt_labels,
    const float* __restrict__ gt_bboxes,
    const float* __restrict__ mask_gt)
{
    int row = blockIdx.y;                  // b*MM + m
    if (mask_gt[row] <= 0.f) return;
    int t = blockIdx.x * 256 + threadIdx.x;

    float4 g = reinterpret_cast<const float4*>(gt_bboxes)[row];

    int ix0s[3], iy0s[3], ws[3];
    int tot = 0, t0 = 0, t1 = 0;
    #pragma unroll
    for (int ks = 0; ks < 3; ++ks) {
        const int   n = (ks == 0) ? 80 : (ks == 1) ? 40 : 20;
        const float s = (ks == 0) ? 8.f : (ks == 1) ? 16.f : 32.f;
        int ix0 = max(0,     (int)floorf(g.x / s - 0.5f));
        int ix1 = min(n - 1, (int)floorf(g.z / s - 0.5f) + 1);
        int iy0 = max(0,     (int)floorf(g.y / s - 0.5f));
        int iy1 = min(n - 1, (int)floorf(g.w / s - 0.5f) + 1);
        int w = max(ix1 - ix0 + 1, 0), h = max(iy1 - iy0 + 1, 0);
        ix0s[ks] = ix0; iy0s[ks] = iy0; ws[ks] = w;
        if (ks == 0) t0 = w * h;
        if (ks == 1) t1 = w * h;
        tot += w * h;
    }
    if (t >= tot) return;

    int ks, tc;
    if (t < t0)            { ks = 0; tc = t; }
    else if (t < t0 + t1)  { ks = 1; tc = t - t0; }
    else                   { ks = 2; tc = t - t0 - t1; }
    const int   n   = (ks == 0) ? 80 : (ks == 1) ? 40 : 20;
    const float s   = (ks == 0) ? 8.f : (ks == 1) ? 16.f : 32.f;
    const int   off = (ks == 0) ? 0 : (ks == 1) ? 6400 : 8000;
    int ix = ix0s[ks] + tc % ws[ks];
    int iy = iy0s[ks] + tc / ws[ks];
    float ax = (ix + 0.5f) * s, ay = (iy + 0.5f) * s;
    if (dmin_xy(g, ax, ay) <= EPS9) return;

    int b = row >> 7;
    int idx = off + iy * n + ix;
    float at1 = atanf((g.z - g.x) / (g.w - g.y + EPS7));
    float4 p = reinterpret_cast<const float4*>(pd_bboxes)[(size_t)b * NA + idx];
    float ov = ciou_hg(g, p, at1);
    if (ov <= 0.f) return;
    int lbl = gt_labels[row];
    float sc = pd_scores[((size_t)b * NA + idx) * NC + lbl];
    float o2 = ov * ov;
    float al = sc * (o2 * o2 * o2);
    if (al <= 0.f) return;

    int slot = atomicAdd(&g_ccount[row], 1);
    if (slot < CAP)
        g_cand[(size_t)row * CAP + slot] =
            ((unsigned long long)__float_as_uint(al) << 32) |
            (unsigned)(0x7fffffff - idx);
}

// ---------------------------------------------------------------------------
// K1b: one WARP per row: top-13 over candidate keys (value desc, index asc),
// claims carry al + ov.
// ---------------------------------------------------------------------------
__global__ __launch_bounds__(256) void k1b(
    const float* __restrict__ pd_bboxes,
    const float* __restrict__ gt_bboxes,
    const float* __restrict__ mask_gt)
{
    int wid = threadIdx.x >> 5, lane = threadIdx.x & 31;
    int row = blockIdx.x * 8 + wid;
    if (row >= BS * MM) return;
    if (mask_gt[row] <= 0.f) return;
    int b = row >> 7, m = row & 127;

    int ncand = min(g_ccount[row], CAP);
    const unsigned long long* cp = g_cand + (size_t)row * CAP;

    unsigned long long keys[KTOP];
    #pragma unroll
    for (int j = 0; j < KTOP; ++j) keys[j] = 0ull;

    for (int j = lane; j < ncand; j += 32) {
        unsigned long long ck = cp[j];
        if (ck > keys[KTOP - 1]) {
            #pragma unroll
            for (int q = 0; q < KTOP; ++q) {
                unsigned long long kq = keys[q];
                if (ck > kq) { keys[q] = ck; ck = kq; }
            }
        }
    }

    int   mysel = -1;
    float myval = 0.f;
    int qsel = 0;
    #pragma unroll 1
    for (int it = 0; it < KTOP; ++it) {
        unsigned long long k = keys[0];
        #pragma unroll
        for (int d = 16; d; d >>= 1) {
            unsigned long long o = __shfl_xor_sync(FULL, k, d);
            if (o > k) k = o;
        }
        if ((unsigned)(k >> 32) == 0u) break;
        if (lane == qsel) {
            mysel = 0x7fffffff - (int)(k & 0xffffffffu);
            myval = __uint_as_float((unsigned)(k >> 32));
        }
        qsel++;
        if (keys[0] == k) {
            #pragma unroll
            for (int j = 0; j < KTOP - 1; ++j) keys[j] = keys[j + 1];
            keys[KTOP - 1] = 0ull;
        }
    }

    float4 g = reinterpret_cast<const float4*>(gt_bboxes)[row];

    if (lane < qsel) {
        float at1 = atanf((g.z - g.x) / (g.w - g.y + EPS7));
        float4 p = reinterpret_cast<const float4*>(pd_bboxes)[(size_t)b * NA + mysel];
        float ov = ciou_hg(g, p, at1);
        atomicAdd(&g_cs   [b * NA + mysel], CNT1 | m);
        atomicAdd(&g_alsum[b * NA + mysel], myval);
        atomicAdd(&g_ovsum[b * NA + mysel], ov);
    }

    // zero-fill (rare): smallest-index zero-valued anchors of the full row
    if (qsel < KTOP) {
        int sarr[KTOP];
        for (int t = 0; t < qsel; ++t)
            sarr[t] = __shfl_sync(FULL, mysel, t);
        if (lane == 0) {
            float at1 = atanf((g.z - g.x) / (g.w - g.y + EPS7));
            const float4* pbb = reinterpret_cast<const float4*>(pd_bboxes) + (size_t)b * NA;
            int need = KTOP - qsel;
            int j = 0;
            while (need > 0 && j < 8 * KTOP) {
                bool ispos = false;
                for (int t = 0; t < qsel; ++t) if (sarr[t] == j) { ispos = true; break; }
                if (!ispos) {
                    int ix = j % 80, iy = j / 80;   // j small -> scale-8 grid
                    float ax = (ix + 0.5f) * 8.f, ay = (iy + 0.5f) * 8.f;
                    if (dmin_xy(g, ax, ay) > EPS9) {
                        float ov = ciou_hg(g, pbb[j], at1);
                        atomicAdd(&g_cs   [b * NA + j], CNT1 | m);
                        atomicAdd(&g_ovsum[b * NA + j], ov);
                    }
                    need--;
                }
                j++;
            }
        }
    }
}

// ---------------------------------------------------------------------------
// K3a: per (b,a). cnt<=1 resolved with carried sums; lists appended with
// warp-aggregated atomics (one counter atomic per warp); multi entries
// seed g_best with key(v=0, m=0).
// ---------------------------------------------------------------------------
__global__ __launch_bounds__(256) void k3a(float* __restrict__ out)
{
    int idx = blockIdx.x * blockDim.x + threadIdx.x;
    if (idx >= BS * NA) return;
    int lane = threadIdx.x & 31;
    int b = idx / NA;

    int cs = g_cs[idx];
    int cnt = cs >> 20;
    bool is_multi = cnt > 1;
    bool is_fg1   = cnt == 1;

    unsigned mmask = __ballot_sync(FULL, is_multi);
    if (mmask) {
        int leader = __ffs(mmask) - 1;
        int base = 0;
        if (lane == leader) base = atomicAdd(&g_nmulti, __popc(mmask));
        base = __shfl_sync(FULL, base, leader);
        if (is_multi) {
            int p = base + __popc(mmask & ((1u << lane) - 1));
            g_multilist[p] = idx;
            g_best[p] = (unsigned long long)(MM - 1);   // v=0, m=0 default
        }
    }
    unsigned fmask = __ballot_sync(FULL, is_fg1);
    if (fmask) {
        int leader = __ffs(fmask) - 1;
        int base = 0;
        if (lane == leader) base = atomicAdd(&g_nfg, __popc(fmask));
        base = __shfl_sync(FULL, base, leader);
        if (is_fg1)
            g_fglist[base + __popc(fmask & ((1u << lane) - 1))] = idx;
    }
    if (is_multi) return;                  // outputs written by k3b2

    int fg = cnt, tgt = 0;
    float al = 0.f;
    if (is_fg1) {
        tgt = cs & 0xfffff;
        al  = g_alsum[idx];
        float ovm = g_ovsum[idx];
        int row = b * MM + tgt;
        atomicMax((unsigned int*)&g_pos_am[row], __float_as_uint(al));
        atomicMax((unsigned int*)&g_pos_ov[row], __float_as_uint(ovm));
    }
    g_tgt[idx] = tgt;
    g_al [idx] = al;

    int grow = b * MM + tgt;
    int lbl = max(__float_as_int(g_gtaux[grow].z), 0);
    float4 bx = g_gtbox[grow];
    float* o_lab = out;
    float* o_box = out + (size_t)BS * NA;
    float* o_fg  = out + (size_t)BS * NA * (5 + NC);
    float* o_tg  = o_fg + (size_t)BS * NA;
    o_lab[idx] = (float)lbl;
    reinterpret_cast<float4*>(o_box)[idx] = bx;
    o_fg[idx] = fg ? 1.f : 0.f;
    o_tg[idx] = (float)tgt;
}

// ---------------------------------------------------------------------------
// K3b1: one THREAD per (entry, m): masked CIoU; atomicMax packed key
// (val<<32 | (MM-1-m)) only when v>0.
// ---------------------------------------------------------------------------
__global__ __launch_bounds__(256) void k3b1(
    const float* __restrict__ pd_bboxes,
    const float* __restrict__ anc)
{
    int tot = g_nmulti * MM;
    int stride = gridDim.x * blockDim.x;
    for (int t = blockIdx.x * blockDim.x + threadIdx.x; t < tot; t += stride) {
        int e = t >> 7, m = t & 127;
        int idx = g_multilist[e];
        int b = idx / NA, a = idx - b * NA;
        int row = b * MM + m;
        float4 aux = g_gtaux[row];
        if (aux.y <= 0.f) continue;
        float2 an = reinterpret_cast<const float2*>(anc)[a];
        float4 gg = g_gtbox[row];
        if (dmin_xy(gg, an.x, an.y) <= EPS9) continue;
        float4 p = reinterpret_cast<const float4*>(pd_bboxes)[idx];
        float at2 = atanf((p.z - p.x) / (p.w - p.y + EPS7));
        float v = ciou_core(gg, p, aux.x, at2);
        if (v > 0.f) {
            unsigned long long key =
                ((unsigned long long)__float_as_uint(v) << 32) |
                (unsigned)(MM - 1 - m);
            atomicMax(&g_best[e], key);
        }
    }
}

// ---------------------------------------------------------------------------
// K3b2: one thread per entry: unpack winner, finish entry.
// ---------------------------------------------------------------------------
__global__ __launch_bounds__(256) void k3b2(
    const float* __restrict__ pd_scores,
    float* __restrict__ out)
{
    int nm = g_nmulti;
    int stride = gridDim.x * blockDim.x;
    for (int e = blockIdx.x * blockDim.x + threadIdx.x; e < nm; e += stride) {
        int idx = g_multilist[e];
        int b = idx / NA, a = idx - b * NA;
        unsigned long long k = g_best[e];
        int tgt = MM - 1 - (int)(k & 0xffffffffu);
        float ovm = __uint_as_float((unsigned)(k >> 32));
        int row = b * MM + tgt;
        int lbl = __float_as_int(g_gtaux[row].z);
        float al = 0.f;
        if (ovm > 0.f) {
            float sc = pd_scores[((size_t)b * NA + a) * NC + lbl];
            float o2 = ovm * ovm;
            al = sc * (o2 * o2 * o2);
        }
        atomicMax((unsigned int*)&g_pos_am[row], __float_as_uint(al));
        atomicMax((unsigned int*)&g_pos_ov[row], __float_as_uint(ovm));
        g_tgt[idx] = tgt;
        g_al [idx] = al;
        int qq = atomicAdd(&g_nfg, 1);
        g_fglist[qq] = idx;

        float4 bx = g_gtbox[row];
        float* o_lab = out;
        float* o_box = out + (size_t)BS * NA;
        float* o_fg  = out + (size_t)BS * NA * (5 + NC);
        float* o_tg  = o_fg + (size_t)BS * NA;
        o_lab[idx] = (float)max(lbl, 0);
        reinterpret_cast<float4*>(o_box)[idx] = bx;
        o_fg[idx] = 1.f;
        o_tg[idx] = (float)tgt;
    }
}

// ---------------------------------------------------------------------------
// K4: sparse nrm scatter over the compacted fg list (scores pre-zeroed)
// ---------------------------------------------------------------------------
__global__ __launch_bounds__(256) void k4_scatter(float* __restrict__ out)
{
    float* o_sc = out + (size_t)BS * NA * 5;
    int nfg = g_nfg;
    int stride = gridDim.x * blockDim.x;
    for (int i = blockIdx.x * blockDim.x + threadIdx.x; i < nfg; i += stride) {
        int idx = g_fglist[i];
        int b = idx / NA;
        int tgt = g_tgt[idx];
        int grow = b * MM + tgt;
        int lbl = max(__float_as_int(g_gtaux[grow].z), 0);
        float nrm = g_al[idx] * g_pos_ov[grow] / (g_pos_am[grow] + EPS9);
        o_sc[(size_t)idx * NC + lbl] = nrm;
    }
}

// ---------------------------------------------------------------------------
extern "C" void kernel_launch(void* const* d_in, const int* in_sizes, int n_in,
                              void* d_out, int out_size)
{
    const float* pd_scores = (const float*)d_in[0];
    const float* pd_bboxes = (const float*)d_in[1];
    const float* anc       = (const float*)d_in[2];
    const int*   gt_labels = (const int*)  d_in[3];
    const float* gt_bboxes = (const float*)d_in[4];
    const float* mask_gt   = (const float*)d_in[5];
    float* out = (float*)d_out;

    // side stream for the big output-zeroing memset (fork/join in the graph)
    static cudaStream_t s2 = nullptr;
    static cudaEvent_t evFork = nullptr, evJoin = nullptr;
    if (!s2) {
        cudaStreamCreateWithFlags(&s2, cudaStreamNonBlocking);
        cudaEventCreateWithFlags(&evFork, cudaEventDisableTiming);
        cudaEventCreateWithFlags(&evJoin, cudaEventDisableTiming);
    }

    float* o_sc = out + (size_t)BS * NA * 5;
    cudaEventRecord(evFork, 0);
    cudaStreamWaitEvent(s2, evFork, 0);
    cudaMemsetAsync(o_sc, 0, (size_t)BS * NA * NC * sizeof(float), s2);
    cudaEventRecord(evJoin, s2);

    int n = BS * NA;
    k0_zero<<<(n + 255) / 256, 256>>>(gt_labels, gt_bboxes, mask_gt);
    k1a<<<dim3(5, BS * MM), 256>>>(pd_scores, pd_bboxes,
                                   gt_labels, gt_bboxes, mask_gt);
    k1b<<<(BS * MM + 7) / 8, 256>>>(pd_bboxes, gt_bboxes, mask_gt);
    k3a<<<(n + 255) / 256, 256>>>(out);
    k3b1<<<2048, 256>>>(pd_bboxes, anc);
    k3b2<<<64, 256>>>(pd_scores, out);

    cudaStreamWaitEvent(0, evJoin, 0);     // memset must finish before scatter
    k4_scatter<<<64, 256>>>(out);
}

// round 12
// speedup vs baseline: 1.3082x; 1.0681x over previous
#include <cuda_runtime.h>
#include <cuda_bf16.h>
#include <stdint.h>

#define BS   16
#define MM   128
#define NA   8400
#define NC   80
#define KTOP 13
#define CAP  1024
#define EPS7 1e-7f
#define EPS9 1e-9f
#define FULL 0xffffffffu
#define CNT1 (1 << 20)   // packed claim increment: cnt in high bits, sum(m) low

// scratch (static device globals -- allowed)
__device__ int    g_cs  [BS * NA];    // packed: (cnt<<20) | sum_of_m
__device__ float  g_alsum[BS * NA];
__device__ float  g_ovsum[BS * NA];
__device__ unsigned long long g_best[BS * NA];
__device__ unsigned long long g_cand[(size_t)BS * MM * CAP];
__device__ int    g_ccount[BS * MM];
__device__ float  g_pos_am[BS * MM];
__device__ float  g_pos_ov[BS * MM];
__device__ int    g_tgt[BS * NA];
__device__ float  g_al [BS * NA];
__device__ int    g_fglist[BS * NA];
__device__ int    g_multilist[BS * NA];
__device__ int    g_touched[BS * NA];
__device__ int    g_nfg;
__device__ int    g_nmulti;
__device__ int    g_ntouched;
__device__ float4 g_gtbox[BS * MM];   // gt box
__device__ float4 g_gtaux[BS * MM];   // {at1, mask, label(int bits), unused}

// ---------------------------------------------------------------------------
// CIoU (identical math to reference _ciou + clip>=0)
// ---------------------------------------------------------------------------
__device__ __forceinline__ float ciou_core(const float4 g, const float4 p,
                                           float at_g, float at_p)
{
    const float c4pi2 = 0.40528473456935108577f;  // 4/pi^2
    float w1 = g.z - g.x, h1 = g.w - g.y + EPS7;
    float w2 = p.z - p.x, h2 = p.w - p.y + EPS7;
    float iw = fminf(g.z, p.z) - fmaxf(g.x, p.x);
    float ih = fminf(g.w, p.w) - fmaxf(g.y, p.y);
    float inter = fmaxf(iw, 0.f) * fmaxf(ih, 0.f);
    float uni = w1 * h1 + w2 * h2 - inter + EPS7;
    float iou = inter / uni;
    float cw = fmaxf(g.z, p.z) - fminf(g.x, p.x);
    float ch = fmaxf(g.w, p.w) - fminf(g.y, p.y);
    float c2 = cw * cw + ch * ch + EPS7;
    float dx = p.x + p.z - g.x - g.z;
    float dy = p.y + p.w - g.y - g.w;
    float rho2 = (dx * dx + dy * dy) * 0.25f;
    float dat = at_p - at_g;
    float v = c4pi2 * dat * dat;
    float alpha = v / (v - iou + (1.f + EPS7));
    return fmaxf(iou - (rho2 / c2 + v * alpha), 0.f);
}
__device__ __forceinline__ float ciou_hg(const float4 g, const float4 p, float at_g)
{
    return ciou_core(g, p, at_g, atanf((p.z - p.x) / (p.w - p.y + EPS7)));
}
__device__ __forceinline__ float dmin_xy(const float4 g, float ax, float ay)
{
    return fminf(fminf(ax - g.x, ay - g.y), fminf(g.z - ax, g.w - ay));
}

// ---------------------------------------------------------------------------
// K0: zero scratch + build GT prep table
// ---------------------------------------------------------------------------
__global__ __launch_bounds__(256) void k0_zero(
    const int*   __restrict__ gt_labels,
    const float* __restrict__ gt_bboxes,
    const float* __restrict__ mask_gt)
{
    int i = blockIdx.x * blockDim.x + threadIdx.x;
    if (i < BS * NA) {
        g_cs[i] = 0;
        g_alsum[i] = 0.f; g_ovsum[i] = 0.f;
    }
    if (i < BS * MM) {
        g_ccount[i] = 0;
        g_pos_am[i] = 0.f; g_pos_ov[i] = 0.f;
        float4 g = reinterpret_cast<const float4*>(gt_bboxes)[i];
        g_gtbox[i] = g;
        float4 aux;
        aux.x = atanf((g.z - g.x) / (g.w - g.y + EPS7));
        aux.y = mask_gt[i];
        aux.z = __int_as_float(gt_labels[i]);
        aux.w = 0.f;
        g_gtaux[i] = aux;
    }
    if (i == 0) { g_nfg = 0; g_nmulti = 0; g_ntouched = 0; }
}

// ---------------------------------------------------------------------------
// KD (side stream): default outputs for ALL anchors: label/box of gt[b][0],
// fg=0, tgt=0. Touched anchors get overwritten by k3s/k3b2.
// ---------------------------------------------------------------------------
__global__ __launch_bounds__(256) void kD(float* __restrict__ out)
{
    int idx = blockIdx.x * blockDim.x + threadIdx.x;
    if (idx >= BS * NA) return;
    int b = idx / NA;
    int grow = b * MM;
    int lbl = max(__float_as_int(g_gtaux[grow].z), 0);
    float4 bx = g_gtbox[grow];

    float* o_lab = out;
    float* o_box = out + (size_t)BS * NA;
    float* o_fg  = out + (size_t)BS * NA * (5 + NC);
    float* o_tg  = o_fg + (size_t)BS * NA;
    o_lab[idx] = (float)lbl;
    reinterpret_cast<float4*>(o_box)[idx] = bx;
    o_fg[idx] = 0.f;
    o_tg[idx] = 0.f;
}

// ---------------------------------------------------------------------------
// K1a: one THREAD per (row, rect-cell). Positive align metrics pushed into
// per-row candidate buffers as packed keys.
// ---------------------------------------------------------------------------
__global__ __launch_bounds__(256) void k1a(
    const float* __restrict__ pd_scores,
    const float* __restrict__ pd_bboxes,
    const int*   __restrict__ gt_labels,
    const float* __restrict__ gt_bboxes,
    const float* __restrict__ mask_gt)
{
    int row = blockIdx.y;                  // b*MM + m
    if (mask_gt[row] <= 0.f) return;
    int t = blockIdx.x * 256 + threadIdx.x;

    float4 g = reinterpret_cast<const float4*>(gt_bboxes)[row];

    int ix0s[3], iy0s[3], ws[3];
    int tot = 0, t0 = 0, t1 = 0;
    #pragma unroll
    for (int ks = 0; ks < 3; ++ks) {
        const int   n = (ks == 0) ? 80 : (ks == 1) ? 40 : 20;
        const float s = (ks == 0) ? 8.f : (ks == 1) ? 16.f : 32.f;
        int ix0 = max(0,     (int)floorf(g.x / s - 0.5f));
        int ix1 = min(n - 1, (int)floorf(g.z / s - 0.5f) + 1);
        int iy0 = max(0,     (int)floorf(g.y / s - 0.5f));
        int iy1 = min(n - 1, (int)floorf(g.w / s - 0.5f) + 1);
        int w = max(ix1 - ix0 + 1, 0), h = max(iy1 - iy0 + 1, 0);
        ix0s[ks] = ix0; iy0s[ks] = iy0; ws[ks] = w;
        if (ks == 0) t0 = w * h;
        if (ks == 1) t1 = w * h;
        tot += w * h;
    }
    if (t >= tot) return;

    int ks, tc;
    if (t < t0)            { ks = 0; tc = t; }
    else if (t < t0 + t1)  { ks = 1; tc = t - t0; }
    else                   { ks = 2; tc = t - t0 - t1; }
    const int   n   = (ks == 0) ? 80 : (ks == 1) ? 40 : 20;
    const float s   = (ks == 0) ? 8.f : (ks == 1) ? 16.f : 32.f;
    const int   off = (ks == 0) ? 0 : (ks == 1) ? 6400 : 8000;
    int ix = ix0s[ks] + tc % ws[ks];
    int iy = iy0s[ks] + tc / ws[ks];
    float ax = (ix + 0.5f) * s, ay = (iy + 0.5f) * s;
    if (dmin_xy(g, ax, ay) <= EPS9) return;

    int b = row >> 7;
    int idx = off + iy * n + ix;
    float at1 = atanf((g.z - g.x) / (g.w - g.y + EPS7));
    float4 p = reinterpret_cast<const float4*>(pd_bboxes)[(size_t)b * NA + idx];
    float ov = ciou_hg(g, p, at1);
    if (ov <= 0.f) return;
    int lbl = gt_labels[row];
    float sc = pd_scores[((size_t)b * NA + idx) * NC + lbl];
    float o2 = ov * ov;
    float al = sc * (o2 * o2 * o2);
    if (al <= 0.f) return;

    int slot = atomicAdd(&g_ccount[row], 1);
    if (slot < CAP)
        g_cand[(size_t)row * CAP + slot] =
            ((unsigned long long)__float_as_uint(al) << 32) |
            (unsigned)(0x7fffffff - idx);
}

// ---------------------------------------------------------------------------
// K1b: one WARP per row: top-13 over candidate keys (value desc, index asc);
// claims carry al + ov, and first claims append to g_touched (dedup).
// ---------------------------------------------------------------------------
__global__ __launch_bounds__(256) void k1b(
    const float* __restrict__ pd_bboxes,
    const float* __restrict__ gt_bboxes,
    const float* __restrict__ mask_gt)
{
    int wid = threadIdx.x >> 5, lane = threadIdx.x & 31;
    int row = blockIdx.x * 8 + wid;
    if (row >= BS * MM) return;
    if (mask_gt[row] <= 0.f) return;
    int b = row >> 7, m = row & 127;

    int ncand = min(g_ccount[row], CAP);
    const unsigned long long* cp = g_cand + (size_t)row * CAP;

    unsigned long long keys[KTOP];
    #pragma unroll
    for (int j = 0; j < KTOP; ++j) keys[j] = 0ull;

    for (int j = lane; j < ncand; j += 32) {
        unsigned long long ck = cp[j];
        if (ck > keys[KTOP - 1]) {
            #pragma unroll
            for (int q = 0; q < KTOP; ++q) {
                unsigned long long kq = keys[q];
                if (ck > kq) { keys[q] = ck; ck = kq; }
            }
        }
    }

    int   mysel = -1;
    float myval = 0.f;
    int qsel = 0;
    #pragma unroll 1
    for (int it = 0; it < KTOP; ++it) {
        unsigned long long k = keys[0];
        #pragma unroll
        for (int d = 16; d; d >>= 1) {
            unsigned long long o = __shfl_xor_sync(FULL, k, d);
            if (o > k) k = o;
        }
        if ((unsigned)(k >> 32) == 0u) break;
        if (lane == qsel) {
            mysel = 0x7fffffff - (int)(k & 0xffffffffu);
            myval = __uint_as_float((unsigned)(k >> 32));
        }
        qsel++;
        if (keys[0] == k) {
            #pragma unroll
            for (int j = 0; j < KTOP - 1; ++j) keys[j] = keys[j + 1];
            keys[KTOP - 1] = 0ull;
        }
    }

    float4 g = reinterpret_cast<const float4*>(gt_bboxes)[row];

    if (lane < qsel) {
        float at1 = atanf((g.z - g.x) / (g.w - g.y + EPS7));
        float4 p = reinterpret_cast<const float4*>(pd_bboxes)[(size_t)b * NA + mysel];
        float ov = ciou_hg(g, p, at1);
        int gidx = b * NA + mysel;
        int old = atomicAdd(&g_cs[gidx], CNT1 | m);
        atomicAdd(&g_alsum[gidx], myval);
        atomicAdd(&g_ovsum[gidx], ov);
        bool first = (old >> 20) == 0;
        unsigned amask = (1u << qsel) - 1u;          // lanes 0..qsel-1 active
        unsigned fm = __ballot_sync(amask, first);
        if (fm) {
            int leader = __ffs(fm) - 1;
            int base = 0;
            if (lane == leader) base = atomicAdd(&g_ntouched, __popc(fm));
            base = __shfl_sync(amask, base, leader);
            if (first)
                g_touched[base + __popc(fm & ((1u << lane) - 1))] = gidx;
        }
    }

    // zero-fill (rare): smallest-index zero-valued anchors of the full row
    if (qsel < KTOP) {
        int sarr[KTOP];
        for (int t = 0; t < qsel; ++t)
            sarr[t] = __shfl_sync(FULL, mysel, t);
        if (lane == 0) {
            float at1 = atanf((g.z - g.x) / (g.w - g.y + EPS7));
            const float4* pbb = reinterpret_cast<const float4*>(pd_bboxes) + (size_t)b * NA;
            int need = KTOP - qsel;
            int j = 0;
            while (need > 0 && j < 8 * KTOP) {
                bool ispos = false;
                for (int t = 0; t < qsel; ++t) if (sarr[t] == j) { ispos = true; break; }
                if (!ispos) {
                    int ix = j % 80, iy = j / 80;   // j small -> scale-8 grid
                    float ax = (ix + 0.5f) * 8.f, ay = (iy + 0.5f) * 8.f;
                    if (dmin_xy(g, ax, ay) > EPS9) {
                        float ov = ciou_hg(g, pbb[j], at1);
                        int gidx = b * NA + j;
                        int old = atomicAdd(&g_cs[gidx], CNT1 | m);
                        atomicAdd(&g_ovsum[gidx], ov);
                        if ((old >> 20) == 0) {
                            int p = atomicAdd(&g_ntouched, 1);
                            g_touched[p] = gidx;
                        }
                    }
                    need--;
                }
                j++;
            }
        }
    }
}

// ---------------------------------------------------------------------------
// K3s: sparse pass over touched anchors only. cnt==1 resolved inline with
// carried sums (overwrites defaults); cnt>1 compacted for k3b.
// ---------------------------------------------------------------------------
__global__ __launch_bounds__(256) void k3s(float* __restrict__ out)
{
    int nt = g_ntouched;
    int R = (nt + 31) & ~31;               // warp-uniform loop bound
    int lane = threadIdx.x & 31;
    int stride = gridDim.x * blockDim.x;

    for (int i = blockIdx.x * blockDim.x + threadIdx.x; i < R; i += stride) {
        bool valid = i < nt;
        int idx = valid ? g_touched[i] : 0;
        int cs  = valid ? g_cs[idx] : 0;
        int cnt = cs >> 20;
        bool is_multi = valid && cnt > 1;
        bool is_fg1   = valid && cnt == 1;

        unsigned mmask = __ballot_sync(FULL, is_multi);
        if (mmask) {
            int leader = __ffs(mmask) - 1;
            int base = 0;
            if (lane == leader) base = atomicAdd(&g_nmulti, __popc(mmask));
            base = __shfl_sync(FULL, base, leader);
            if (is_multi) {
                int p = base + __popc(mmask & ((1u << lane) - 1));
                g_multilist[p] = idx;
                g_best[p] = (unsigned long long)(MM - 1);   // v=0, m=0
            }
        }
        unsigned fmask = __ballot_sync(FULL, is_fg1);
        if (fmask) {
            int leader = __ffs(fmask) - 1;
            int base = 0;
            if (lane == leader) base = atomicAdd(&g_nfg, __popc(fmask));
            base = __shfl_sync(FULL, base, leader);
            if (is_fg1)
                g_fglist[base + __popc(fmask & ((1u << lane) - 1))] = idx;
        }

        if (is_fg1) {
            int b = idx / NA;
            int tgt = cs & 0xfffff;
            float al  = g_alsum[idx];
            float ovm = g_ovsum[idx];
            int row = b * MM + tgt;
            atomicMax((unsigned int*)&g_pos_am[row], __float_as_uint(al));
            atomicMax((unsigned int*)&g_pos_ov[row], __float_as_uint(ovm));
            g_tgt[idx] = tgt;
            g_al [idx] = al;

            int lbl = max(__float_as_int(g_gtaux[row].z), 0);
            float4 bx = g_gtbox[row];
            float* o_lab = out;
            float* o_box = out + (size_t)BS * NA;
            float* o_fg  = out + (size_t)BS * NA * (5 + NC);
            float* o_tg  = o_fg + (size_t)BS * NA;
            o_lab[idx] = (float)lbl;
            reinterpret_cast<float4*>(o_box)[idx] = bx;
            o_fg[idx] = 1.f;
            o_tg[idx] = (float)tgt;
        }
    }
}

// ---------------------------------------------------------------------------
// K3b1: one THREAD per (entry, m): masked CIoU; atomicMax packed key
// (val<<32 | (MM-1-m)) only when v>0.
// ---------------------------------------------------------------------------
__global__ __launch_bounds__(256) void k3b1(
    const float* __restrict__ pd_bboxes,
    const float* __restrict__ anc)
{
    int tot = g_nmulti * MM;
    int stride = gridDim.x * blockDim.x;
    for (int t = blockIdx.x * blockDim.x + threadIdx.x; t < tot; t += stride) {
        int e = t >> 7, m = t & 127;
        int idx = g_multilist[e];
        int b = idx / NA, a = idx - b * NA;
        int row = b * MM + m;
        float4 aux = g_gtaux[row];
        if (aux.y <= 0.f) continue;
        float2 an = reinterpret_cast<const float2*>(anc)[a];
        float4 gg = g_gtbox[row];
        if (dmin_xy(gg, an.x, an.y) <= EPS9) continue;
        float4 p = reinterpret_cast<const float4*>(pd_bboxes)[idx];
        float at2 = atanf((p.z - p.x) / (p.w - p.y + EPS7));
        float v = ciou_core(gg, p, aux.x, at2);
        if (v > 0.f) {
            unsigned long long key =
                ((unsigned long long)__float_as_uint(v) << 32) |
                (unsigned)(MM - 1 - m);
            atomicMax(&g_best[e], key);
        }
    }
}

// ---------------------------------------------------------------------------
// K3b2: one thread per entry: unpack winner, finish entry (overwrites
// defaults).
// ---------------------------------------------------------------------------
__global__ __launch_bounds__(256) void k3b2(
    const float* __restrict__ pd_scores,
    float* __restrict__ out)
{
    int nm = g_nmulti;
    int stride = gridDim.x * blockDim.x;
    for (int e = blockIdx.x * blockDim.x + threadIdx.x; e < nm; e += stride) {
        int idx = g_multilist[e];
        int b = idx / NA, a = idx - b * NA;
        unsigned long long k = g_best[e];
        int tgt = MM - 1 - (int)(k & 0xffffffffu);
        float ovm = __uint_as_float((unsigned)(k >> 32));
        int row = b * MM + tgt;
        int lbl = __float_as_int(g_gtaux[row].z);
        float al = 0.f;
        if (ovm > 0.f) {
            float sc = pd_scores[((size_t)b * NA + a) * NC + lbl];
            float o2 = ovm * ovm;
            al = sc * (o2 * o2 * o2);
        }
        atomicMax((unsigned int*)&g_pos_am[row], __float_as_uint(al));
        atomicMax((unsigned int*)&g_pos_ov[row], __float_as_uint(ovm));
        g_tgt[idx] = tgt;
        g_al [idx] = al;
        int qq = atomicAdd(&g_nfg, 1);
        g_fglist[qq] = idx;

        float4 bx = g_gtbox[row];
        float* o_lab = out;
        float* o_box = out + (size_t)BS * NA;
        float* o_fg  = out + (size_t)BS * NA * (5 + NC);
        float* o_tg  = o_fg + (size_t)BS * NA;
        o_lab[idx] = (float)max(lbl, 0);
        reinterpret_cast<float4*>(o_box)[idx] = bx;
        o_fg[idx] = 1.f;
        o_tg[idx] = (float)tgt;
    }
}

// ---------------------------------------------------------------------------
// K4: sparse nrm scatter over the compacted fg list (scores pre-zeroed)
// ---------------------------------------------------------------------------
__global__ __launch_bounds__(256) void k4_scatter(float* __restrict__ out)
{
    float* o_sc = out + (size_t)BS * NA * 5;
    int nfg = g_nfg;
    int stride = gridDim.x * blockDim.x;
    for (int i = blockIdx.x * blockDim.x + threadIdx.x; i < nfg; i += stride) {
        int idx = g_fglist[i];
        int b = idx / NA;
        int tgt = g_tgt[idx];
        int grow = b * MM + tgt;
        int lbl = max(__float_as_int(g_gtaux[grow].z), 0);
        float nrm = g_al[idx] * g_pos_ov[grow] / (g_pos_am[grow] + EPS9);
        o_sc[(size_t)idx * NC + lbl] = nrm;
    }
}

// ---------------------------------------------------------------------------
extern "C" void kernel_launch(void* const* d_in, const int* in_sizes, int n_in,
                              void* d_out, int out_size)
{
    const float* pd_scores = (const float*)d_in[0];
    const float* pd_bboxes = (const float*)d_in[1];
    const float* anc       = (const float*)d_in[2];
    const int*   gt_labels = (const int*)  d_in[3];
    const float* gt_bboxes = (const float*)d_in[4];
    const float* mask_gt   = (const float*)d_in[5];
    float* out = (float*)d_out;

    static cudaStream_t s2 = nullptr;
    static cudaEvent_t evFork = nullptr, evJoin = nullptr;
    if (!s2) {
        cudaStreamCreateWithFlags(&s2, cudaStreamNonBlocking);
        cudaEventCreateWithFlags(&evFork, cudaEventDisableTiming);
        cudaEventCreateWithFlags(&evJoin, cudaEventDisableTiming);
    }

    float* o_sc = out + (size_t)BS * NA * 5;
    int n = BS * NA;

    // main: prep
    k0_zero<<<(n + 255) / 256, 256>>>(gt_labels, gt_bboxes, mask_gt);

    // side: defaults (needs gt tables) + score memset, overlapped with k1
    cudaEventRecord(evFork, 0);
    cudaStreamWaitEvent(s2, evFork, 0);
    kD<<<(n + 255) / 256, 256, 0, s2>>>(out);
    cudaMemsetAsync(o_sc, 0, (size_t)BS * NA * NC * sizeof(float), s2);
    cudaEventRecord(evJoin, s2);

    // main
    k1a<<<dim3(5, BS * MM), 256>>>(pd_scores, pd_bboxes,
                                   gt_labels, gt_bboxes, mask_gt);
    k1b<<<(BS * MM + 7) / 8, 256>>>(pd_bboxes, gt_bboxes, mask_gt);

    cudaStreamWaitEvent(0, evJoin, 0);     // defaults + memset complete
    k3s<<<128, 256>>>(out);
    k3b1<<<2048, 256>>>(pd_bboxes, anc);
    k3b2<<<64, 256>>>(pd_scores, out);
    k4_scatter<<<64, 256>>>(out);
}